// round 1
// baseline (speedup 1.0000x reference)
#include <cuda_runtime.h>
#include <math.h>

#define B_   2
#define T_   1024
#define C_   1024
#define NH   16
#define NKV  4
#define HD   64
#define S_   2048
#define ROWS 2048           // B*T
#define KVW  (NKV*HD)       // 256

// ---------------- scratch (no allocs allowed) ----------------
__device__ float g_q [ROWS * C_];    // [row][h*64+d]  (RoPE'd in place)
__device__ float g_kn[ROWS * KVW];   // new K rows     (RoPE'd in place)
__device__ float g_vn[ROWS * KVW];   // new V rows
__device__ float g_ao[ROWS * C_];    // attention output, [row][h*64+d]

// ---------------- SGEMM: C[M,N] = A[M,K] @ B[K,N], 128x128 tile, 8x8/thread ----------------
__global__ __launch_bounds__(256) void sgemm_k(const float* __restrict__ A,
                                               const float* __restrict__ Bm,
                                               float* __restrict__ Cm,
                                               int M, int N, int K) {
    __shared__ float a_s[8][128];
    __shared__ float b_s[8][128];
    const int tid = threadIdx.x;
    const int tx = tid & 15, ty = tid >> 4;
    const int m0 = blockIdx.y * 128, n0 = blockIdx.x * 128;
    const int arow = tid >> 1, ahalf = tid & 1;
    const int brow = tid >> 5, bcol = (tid & 31) << 2;

    float acc[8][8];
    #pragma unroll
    for (int i = 0; i < 8; i++)
        #pragma unroll
        for (int j = 0; j < 8; j++) acc[i][j] = 0.f;

    for (int kt = 0; kt < K; kt += 8) {
        float4 av = *(const float4*)&A[(size_t)(m0 + arow) * K + kt + ahalf * 4];
        a_s[ahalf*4+0][arow] = av.x;
        a_s[ahalf*4+1][arow] = av.y;
        a_s[ahalf*4+2][arow] = av.z;
        a_s[ahalf*4+3][arow] = av.w;
        *(float4*)&b_s[brow][bcol] = *(const float4*)&Bm[(size_t)(kt + brow) * N + n0 + bcol];
        __syncthreads();
        #pragma unroll
        for (int kk = 0; kk < 8; kk++) {
            float4 a0 = *(float4*)&a_s[kk][ty*8];
            float4 a1 = *(float4*)&a_s[kk][ty*8+4];
            float4 b0 = *(float4*)&b_s[kk][tx*8];
            float4 b1 = *(float4*)&b_s[kk][tx*8+4];
            float ar[8] = {a0.x,a0.y,a0.z,a0.w,a1.x,a1.y,a1.z,a1.w};
            float br[8] = {b0.x,b0.y,b0.z,b0.w,b1.x,b1.y,b1.z,b1.w};
            #pragma unroll
            for (int i = 0; i < 8; i++)
                #pragma unroll
                for (int j = 0; j < 8; j++)
                    acc[i][j] = fmaf(ar[i], br[j], acc[i][j]);
        }
        __syncthreads();
    }
    #pragma unroll
    for (int i = 0; i < 8; i++) {
        float* cr = &Cm[(size_t)(m0 + ty*8 + i) * N + n0 + tx*8];
        *(float4*)(cr)   = make_float4(acc[i][0], acc[i][1], acc[i][2], acc[i][3]);
        *(float4*)(cr+4) = make_float4(acc[i][4], acc[i][5], acc[i][6], acc[i][7]);
    }
}

// ---------------- RoPE (q: 16 heads, k_new: 4 heads), in place ----------------
// pos = clip(position_indices[b,t] + t + CACHE_LEN, 0, 4095)
// inv_freq computed in double to bit-match numpy float32 powf.
__global__ void rope_k(const int* __restrict__ pidx) {
    __shared__ float invf[32];
    if (threadIdx.x < 32)
        invf[threadIdx.x] = (float)pow(10000.0, -(double)threadIdx.x / 32.0);
    __syncthreads();

    int idx = blockIdx.x * blockDim.x + threadIdx.x;
    if (idx >= ROWS * 20 * 32) return;
    int i   = idx & 31;
    int hs  = (idx >> 5) % 20;
    int row = idx / (20 * 32);
    int t   = row & (T_ - 1);
    int p   = pidx[row] + t + 1024;
    p = min(max(p, 0), 4095);
    float ang = (float)p * invf[i];
    float c = cosf(ang), s = sinf(ang);
    float* base = (hs < 16) ? (g_q + (size_t)row * C_ + hs * HD)
                            : (g_kn + (size_t)row * KVW + (hs - 16) * HD);
    float x1 = base[i], x2 = base[i + 32];
    base[i]      = x1 * c - x2 * s;
    base[i + 32] = x2 * c + x1 * s;
}

// ---------------- KV assembly: cache copy + new rows into output layout [B,NKV,S,HD] ----------------
__global__ void assemble_kv_k(const float* __restrict__ kc, const float* __restrict__ vc,
                              float* __restrict__ kout, float* __restrict__ vout) {
    int idx = blockIdx.x * blockDim.x + threadIdx.x;
    if (idx >= B_ * NKV * S_ * HD) return;
    int d  = idx & 63;
    int s  = (idx >> 6) & (S_ - 1);
    int bk = idx >> 17;             // b*NKV + kv
    if (s < 1024) {
        int src = (bk * 1024 + s) * HD + d;
        kout[idx] = kc[src];
        vout[idx] = vc[src];
    } else {
        int b = bk >> 2, kv = bk & 3;
        int t = s - 1024;
        int src = (b * T_ + t) * KVW + kv * HD + d;
        kout[idx] = g_kn[src];
        vout[idx] = g_vn[src];
    }
}

__device__ __forceinline__ float rmax16(float v) {
    v = fmaxf(v, __shfl_xor_sync(0xffffffffu, v, 8));
    v = fmaxf(v, __shfl_xor_sync(0xffffffffu, v, 4));
    v = fmaxf(v, __shfl_xor_sync(0xffffffffu, v, 2));
    v = fmaxf(v, __shfl_xor_sync(0xffffffffu, v, 1));
    return v;
}
__device__ __forceinline__ float rsum16(float v) {
    v += __shfl_xor_sync(0xffffffffu, v, 8);
    v += __shfl_xor_sync(0xffffffffu, v, 4);
    v += __shfl_xor_sync(0xffffffffu, v, 2);
    v += __shfl_xor_sync(0xffffffffu, v, 1);
    return v;
}

// ---------------- Flash attention: 64q x 64k tiles, 4x4/thread, online softmax ----------------
// grid (16 qtiles, 16 heads, 2 batch), 256 threads.
__global__ __launch_bounds__(256) void attn_k(const float* __restrict__ kall,
                                              const float* __restrict__ vall) {
    extern __shared__ float sm[];
    float* qT  = sm;                 // [64 d][64 q]  (pre-scaled)
    float* kT  = sm + 64 * 64;       // [64 d][68 k]  (reused as pT [64 k][68 q])
    float* v_s = kT + 64 * 68;       // [64 k][64 d]

    const int tid = threadIdx.x;
    const int tx = tid & 15, ty = tid >> 4;
    const int qt = blockIdx.x, h = blockIdx.y, b = blockIdx.z;
    const int kv = h >> 2;
    const float* kb = kall + (size_t)(b * NKV + kv) * S_ * HD;
    const float* vb = vall + (size_t)(b * NKV + kv) * S_ * HD;

    // load Q tile transposed (and fold in the 1/8 scale)
    for (int idx = tid; idx < 64 * 16; idx += 256) {
        int qi = idx >> 4, d4 = (idx & 15) << 2;
        float4 v = *(const float4*)(g_q + (size_t)(b * T_ + qt * 64 + qi) * C_ + h * HD + d4);
        qT[(d4+0)*64 + qi] = v.x * 0.125f;
        qT[(d4+1)*64 + qi] = v.y * 0.125f;
        qT[(d4+2)*64 + qi] = v.z * 0.125f;
        qT[(d4+3)*64 + qi] = v.w * 0.125f;
    }

    float m[4], l[4], o[4][4];
    #pragma unroll
    for (int i = 0; i < 4; i++) {
        m[i] = -1e30f; l[i] = 0.f;
        #pragma unroll
        for (int j = 0; j < 4; j++) o[i][j] = 0.f;
    }

    for (int c0 = 0; c0 < S_; c0 += 64) {
        __syncthreads();  // previous-iteration readers done (also covers qT fill)
        for (int idx = tid; idx < 64 * 16; idx += 256) {
            int ki = idx >> 4, d4 = (idx & 15) << 2;
            float4 kq = *(const float4*)&kb[(size_t)(c0 + ki) * HD + d4];
            kT[(d4+0)*68 + ki] = kq.x;
            kT[(d4+1)*68 + ki] = kq.y;
            kT[(d4+2)*68 + ki] = kq.z;
            kT[(d4+3)*68 + ki] = kq.w;
            *(float4*)&v_s[ki*64 + d4] = *(const float4*)&vb[(size_t)(c0 + ki) * HD + d4];
        }
        __syncthreads();

        // S = Qs @ K^T  (4x4 per thread)
        float s[4][4];
        #pragma unroll
        for (int i = 0; i < 4; i++)
            #pragma unroll
            for (int j = 0; j < 4; j++) s[i][j] = 0.f;
        #pragma unroll 8
        for (int kk = 0; kk < 64; kk++) {
            float4 qf = *(float4*)&qT[kk*64 + ty*4];
            float4 kf = *(float4*)&kT[kk*68 + tx*4];
            float qa[4] = {qf.x, qf.y, qf.z, qf.w};
            float ka[4] = {kf.x, kf.y, kf.z, kf.w};
            #pragma unroll
            for (int i = 0; i < 4; i++)
                #pragma unroll
                for (int j = 0; j < 4; j++)
                    s[i][j] = fmaf(qa[i], ka[j], s[i][j]);
        }

        // online softmax update
        float alpha[4];
        #pragma unroll
        for (int i = 0; i < 4; i++) {
            float mx = fmaxf(fmaxf(s[i][0], s[i][1]), fmaxf(s[i][2], s[i][3]));
            mx = rmax16(mx);
            float mn = fmaxf(m[i], mx);
            alpha[i] = __expf(m[i] - mn);
            m[i] = mn;
            float rs = 0.f;
            #pragma unroll
            for (int j = 0; j < 4; j++) {
                s[i][j] = __expf(s[i][j] - mn);
                rs += s[i][j];
            }
            rs = rsum16(rs);
            l[i] = l[i] * alpha[i] + rs;
            #pragma unroll
            for (int j = 0; j < 4; j++) o[i][j] *= alpha[i];
        }

        __syncthreads();          // stage-1 reads of kT done
        #pragma unroll
        for (int i = 0; i < 4; i++)
            #pragma unroll
            for (int j = 0; j < 4; j++)
                kT[(tx*4 + j) * 68 + ty*4 + i] = s[i][j];   // pT[k][q]
        __syncthreads();

        // O += P @ V
        #pragma unroll 8
        for (int kk = 0; kk < 64; kk++) {
            float4 pf = *(float4*)&kT[kk*68 + ty*4];
            float4 vf = *(float4*)&v_s[kk*64 + tx*4];
            float pa[4] = {pf.x, pf.y, pf.z, pf.w};
            float va[4] = {vf.x, vf.y, vf.z, vf.w};
            #pragma unroll
            for (int i = 0; i < 4; i++)
                #pragma unroll
                for (int j = 0; j < 4; j++)
                    o[i][j] = fmaf(pa[i], va[j], o[i][j]);
        }
    }

    // normalize + write [row][h*64+d]
    #pragma unroll
    for (int i = 0; i < 4; i++) {
        float inv = 1.f / l[i];
        int row = b * T_ + qt * 64 + ty * 4 + i;
        float4 w = make_float4(o[i][0]*inv, o[i][1]*inv, o[i][2]*inv, o[i][3]*inv);
        *(float4*)&g_ao[(size_t)row * C_ + h * HD + tx * 4] = w;
    }
}

// ---------------- launch ----------------
extern "C" void kernel_launch(void* const* d_in, const int* in_sizes, int n_in,
                              void* d_out, int out_size) {
    const float* x    = (const float*)d_in[0];
    const float* kc   = (const float*)d_in[1];
    const float* vc   = (const float*)d_in[2];
    const int*   pidx = (const int*)  d_in[3];
    const float* Wq   = (const float*)d_in[4];
    const float* Wk   = (const float*)d_in[5];
    const float* Wv   = (const float*)d_in[6];
    const float* Wo   = (const float*)d_in[7];

    float* out  = (float*)d_out;                     // [2,1024,1024]
    float* kout = out + 2 * 1024 * 1024;             // [2,4,2048,64]
    float* vout = kout + 2 * 4 * 2048 * 64;          // [2,4,2048,64]

    float *gq, *gkn, *gvn, *gao;
    cudaGetSymbolAddress((void**)&gq,  g_q);
    cudaGetSymbolAddress((void**)&gkn, g_kn);
    cudaGetSymbolAddress((void**)&gvn, g_vn);
    cudaGetSymbolAddress((void**)&gao, g_ao);

    // projections
    dim3 gQ(C_ / 128, ROWS / 128);       // (8,16)
    dim3 gKV(KVW / 128, ROWS / 128);     // (2,16)
    sgemm_k<<<gQ, 256>>>(x, Wq, gq,  ROWS, C_,  C_);
    sgemm_k<<<gKV, 256>>>(x, Wk, gkn, ROWS, KVW, C_);
    sgemm_k<<<gKV, 256>>>(x, Wv, gvn, ROWS, KVW, C_);

    // RoPE on q and k_new
    int nrope = ROWS * 20 * 32;
    rope_k<<<(nrope + 255) / 256, 256>>>(pidx);

    // KV cache concat into output layout
    int nkv = B_ * NKV * S_ * HD;
    assemble_kv_k<<<(nkv + 255) / 256, 256>>>(kc, vc, kout, vout);

    // attention
    size_t smem = (size_t)(64 * 64 + 64 * 68 + 64 * 64) * sizeof(float);  // 50176 B
    cudaFuncSetAttribute(attn_k, cudaFuncAttributeMaxDynamicSharedMemorySize, (int)smem);
    dim3 ga(T_ / 64, NH, B_);            // (16,16,2)
    attn_k<<<ga, 256, smem>>>(kout, vout);

    // output projection
    sgemm_k<<<gQ, 256>>>(gao, Wo, out, ROWS, C_, C_);
}

// round 2
// speedup vs baseline: 3.0196x; 3.0196x over previous
#include <cuda_runtime.h>
#include <math.h>

#define B_   2
#define T_   1024
#define C_   1024
#define NH   16
#define NKV  4
#define HD   64
#define S_   2048
#define ROWS 2048           // B*T
#define KVW  (NKV*HD)       // 256

// ---------------- scratch ----------------
__device__ float g_q [ROWS * C_];
__device__ float g_kn[ROWS * KVW];
__device__ float g_vn[ROWS * KVW];
__device__ float g_ao[ROWS * C_];
__device__ float g_invf[32];

// ---------------- helpers ----------------
__device__ __forceinline__ unsigned f2tf(float x) {
    unsigned u;
    asm("cvt.rna.tf32.f32 %0, %1;" : "=r"(u) : "f"(x));
    return u;
}

__device__ __forceinline__ void mma_tf32(float* c,
                                         unsigned a0, unsigned a1, unsigned a2, unsigned a3,
                                         unsigned b0, unsigned b1) {
    asm volatile(
        "mma.sync.aligned.m16n8k8.row.col.f32.tf32.tf32.f32 "
        "{%0,%1,%2,%3}, {%4,%5,%6,%7}, {%8,%9}, {%0,%1,%2,%3};"
        : "+f"(c[0]), "+f"(c[1]), "+f"(c[2]), "+f"(c[3])
        : "r"(a0), "r"(a1), "r"(a2), "r"(a3), "r"(b0), "r"(b1));
}

// ---------------- tf32 GEMM: C[M,N] = A[M,K] @ B[K,N] ----------------
// 128x128 CTA tile, 8 warps (4x2), warp tile 32x64, K-chunk 32, double-buffered smem.
#define AS 36    // A smem row stride (4-bank shift per row; 16B aligned)
#define BS 136   // B smem row stride (8-bank shift per row; 16B aligned)

__global__ __launch_bounds__(256) void gemm_tf32(const float* __restrict__ A,
                                                 const float* __restrict__ Bm,
                                                 float* __restrict__ Cm,
                                                 int M, int N, int K) {
    extern __shared__ unsigned smu[];
    unsigned* A_s = smu;                 // [2][128][AS]
    unsigned* B_s = smu + 2 * 128 * AS;  // [2][32][BS]

    const int tid = threadIdx.x, lane = tid & 31, warp = tid >> 5;
    const int tq = lane >> 2, tr = lane & 3;
    const int wm = warp >> 1, wn = warp & 1;           // 4 x 2 warp grid
    const int m0 = blockIdx.y * 128, n0 = blockIdx.x * 128;

    float acc[2][8][4];
    #pragma unroll
    for (int i = 0; i < 2; i++)
        #pragma unroll
        for (int j = 0; j < 8; j++)
            #pragma unroll
            for (int k = 0; k < 4; k++) acc[i][j][k] = 0.f;

    float4 fa[4], fb[4];

    // prologue: load chunk 0
    #pragma unroll
    for (int i = 0; i < 4; i++) {
        int idx = tid + i * 256;
        fa[i] = *(const float4*)&A[(size_t)(m0 + (idx >> 3)) * K + ((idx & 7) << 2)];
        fb[i] = *(const float4*)&Bm[(size_t)(idx >> 5) * N + n0 + ((idx & 31) << 2)];
    }
    #pragma unroll
    for (int i = 0; i < 4; i++) {
        int idx = tid + i * 256;
        unsigned* pa = &A_s[(idx >> 3) * AS + ((idx & 7) << 2)];
        pa[0] = f2tf(fa[i].x); pa[1] = f2tf(fa[i].y); pa[2] = f2tf(fa[i].z); pa[3] = f2tf(fa[i].w);
        unsigned* pb = &B_s[(idx >> 5) * BS + ((idx & 31) << 2)];
        pb[0] = f2tf(fb[i].x); pb[1] = f2tf(fb[i].y); pb[2] = f2tf(fb[i].z); pb[3] = f2tf(fb[i].w);
    }
    __syncthreads();

    int buf = 0;
    for (int kc = 0; kc < K; kc += 32) {
        bool more = (kc + 32) < K;
        if (more) {
            #pragma unroll
            for (int i = 0; i < 4; i++) {
                int idx = tid + i * 256;
                fa[i] = *(const float4*)&A[(size_t)(m0 + (idx >> 3)) * K + kc + 32 + ((idx & 7) << 2)];
                fb[i] = *(const float4*)&Bm[(size_t)(kc + 32 + (idx >> 5)) * N + n0 + ((idx & 31) << 2)];
            }
        }

        const unsigned* Ab = &A_s[buf * 128 * AS];
        const unsigned* Bb = &B_s[buf * 32 * BS];
        #pragma unroll
        for (int ks = 0; ks < 4; ks++) {
            unsigned a[2][4];
            #pragma unroll
            for (int mt = 0; mt < 2; mt++) {
                const unsigned* p = &Ab[(wm * 32 + mt * 16 + tq) * AS + ks * 8 + tr];
                a[mt][0] = p[0];
                a[mt][1] = p[8 * AS];
                a[mt][2] = p[4];
                a[mt][3] = p[8 * AS + 4];
            }
            #pragma unroll
            for (int nt = 0; nt < 8; nt++) {
                unsigned b0 = Bb[(ks * 8 + tr) * BS + wn * 64 + nt * 8 + tq];
                unsigned b1 = Bb[(ks * 8 + tr + 4) * BS + wn * 64 + nt * 8 + tq];
                mma_tf32(acc[0][nt], a[0][0], a[0][1], a[0][2], a[0][3], b0, b1);
                mma_tf32(acc[1][nt], a[1][0], a[1][1], a[1][2], a[1][3], b0, b1);
            }
        }

        if (more) {
            int nb = buf ^ 1;
            #pragma unroll
            for (int i = 0; i < 4; i++) {
                int idx = tid + i * 256;
                unsigned* pa = &A_s[nb * 128 * AS + (idx >> 3) * AS + ((idx & 7) << 2)];
                pa[0] = f2tf(fa[i].x); pa[1] = f2tf(fa[i].y); pa[2] = f2tf(fa[i].z); pa[3] = f2tf(fa[i].w);
                unsigned* pb = &B_s[nb * 32 * BS + (idx >> 5) * BS + ((idx & 31) << 2)];
                pb[0] = f2tf(fb[i].x); pb[1] = f2tf(fb[i].y); pb[2] = f2tf(fb[i].z); pb[3] = f2tf(fb[i].w);
            }
        }
        __syncthreads();
        buf ^= 1;
    }

    // epilogue
    #pragma unroll
    for (int mt = 0; mt < 2; mt++)
        #pragma unroll
        for (int nt = 0; nt < 8; nt++) {
            int r = m0 + wm * 32 + mt * 16 + tq;
            int c = n0 + wn * 64 + nt * 8 + 2 * tr;
            *(float2*)&Cm[(size_t)r * N + c]       = make_float2(acc[mt][nt][0], acc[mt][nt][1]);
            *(float2*)&Cm[(size_t)(r + 8) * N + c] = make_float2(acc[mt][nt][2], acc[mt][nt][3]);
        }
}

// ---------------- inv_freq table (double precision, once) ----------------
__global__ void invf_init() {
    if (threadIdx.x < 32)
        g_invf[threadIdx.x] = (float)pow(10000.0, -(double)threadIdx.x / 32.0);
}

// ---------------- RoPE: one sincos per (row, i), applied to all 20 head-slices ----------------
__global__ void rope_k(const int* __restrict__ pidx) {
    int idx = blockIdx.x * blockDim.x + threadIdx.x;   // 65536 threads
    if (idx >= ROWS * 32) return;
    int i = idx & 31, row = idx >> 5;
    int t = row & (T_ - 1);
    int p = min(max(pidx[row] + t + 1024, 0), 4095);
    float ang = (float)p * g_invf[i];
    float c, s;
    sincosf(ang, &s, &c);
    float* qb = g_q + (size_t)row * C_;
    #pragma unroll
    for (int h = 0; h < 16; h++) {
        float x1 = qb[h * 64 + i], x2 = qb[h * 64 + i + 32];
        qb[h * 64 + i]      = x1 * c - x2 * s;
        qb[h * 64 + i + 32] = x2 * c + x1 * s;
    }
    float* kb = g_kn + (size_t)row * KVW;
    #pragma unroll
    for (int h = 0; h < 4; h++) {
        float x1 = kb[h * 64 + i], x2 = kb[h * 64 + i + 32];
        kb[h * 64 + i]      = x1 * c - x2 * s;
        kb[h * 64 + i + 32] = x2 * c + x1 * s;
    }
}

// ---------------- KV assembly into output layout [B,NKV,S,HD] ----------------
__global__ void assemble_kv_k(const float* __restrict__ kc, const float* __restrict__ vc,
                              float* __restrict__ kout, float* __restrict__ vout) {
    int idx = blockIdx.x * blockDim.x + threadIdx.x;
    if (idx >= B_ * NKV * S_ * HD) return;
    int d  = idx & 63;
    int s  = (idx >> 6) & (S_ - 1);
    int bk = idx >> 17;
    if (s < 1024) {
        int src = (bk * 1024 + s) * HD + d;
        kout[idx] = kc[src];
        vout[idx] = vc[src];
    } else {
        int b = bk >> 2, kv = bk & 3;
        int src = ((b * T_) + (s - 1024)) * KVW + kv * HD + d;
        kout[idx] = g_kn[src];
        vout[idx] = g_vn[src];
    }
}

// ---------------- Flash attention, mma.sync tf32 ----------------
// CTA: 128 q rows (8 warps x 16), loops S in 64-key chunks.
#define KVP 72   // K_s / V_s row stride (8-bank shift)
#define PP  68   // P_s row stride (4-bank shift)

__global__ __launch_bounds__(256) void attn_k(const float* __restrict__ kall,
                                              const float* __restrict__ vall) {
    extern __shared__ unsigned sm[];
    unsigned* K_s = sm;                  // [64][KVP]
    unsigned* V_s = sm + 64 * KVP;       // [64][KVP]
    unsigned* P_s = sm + 2 * 64 * KVP;   // [8 warps][16][PP]

    const int tid = threadIdx.x, lane = tid & 31, warp = tid >> 5;
    const int tq = lane >> 2, tr = lane & 3;
    const int qt = blockIdx.x, h = blockIdx.y, b = blockIdx.z;
    const float* kb = kall + (size_t)(b * NKV + (h >> 2)) * S_ * HD;
    const float* vb = vall + (size_t)(b * NKV + (h >> 2)) * S_ * HD;
    const int qrow = qt * 128 + warp * 16;

    // Q fragments, scale folded in (kept in registers for the whole kernel)
    unsigned qa[8][4];
    const float* qp = g_q + (size_t)(b * T_ + qrow) * C_ + h * HD;
    #pragma unroll
    for (int ks = 0; ks < 8; ks++) {
        qa[ks][0] = f2tf(qp[(size_t)tq * C_ + ks * 8 + tr] * 0.125f);
        qa[ks][1] = f2tf(qp[(size_t)(tq + 8) * C_ + ks * 8 + tr] * 0.125f);
        qa[ks][2] = f2tf(qp[(size_t)tq * C_ + ks * 8 + tr + 4] * 0.125f);
        qa[ks][3] = f2tf(qp[(size_t)(tq + 8) * C_ + ks * 8 + tr + 4] * 0.125f);
    }

    float m0 = -1e30f, m1 = -1e30f, l0 = 0.f, l1 = 0.f;
    float o[8][4];
    #pragma unroll
    for (int nt = 0; nt < 8; nt++)
        #pragma unroll
        for (int k = 0; k < 4; k++) o[nt][k] = 0.f;

    unsigned* Pw = P_s + warp * 16 * PP;

    for (int c0 = 0; c0 < S_; c0 += 64) {
        __syncthreads();
        #pragma unroll
        for (int i = 0; i < 4; i++) {
            int idx = tid + i * 256;
            int row = idx >> 4, d4 = (idx & 15) << 2;
            float4 kq = *(const float4*)&kb[(size_t)(c0 + row) * HD + d4];
            float4 vq = *(const float4*)&vb[(size_t)(c0 + row) * HD + d4];
            unsigned* pk = &K_s[row * KVP + d4];
            pk[0] = f2tf(kq.x); pk[1] = f2tf(kq.y); pk[2] = f2tf(kq.z); pk[3] = f2tf(kq.w);
            unsigned* pv = &V_s[row * KVP + d4];
            pv[0] = f2tf(vq.x); pv[1] = f2tf(vq.y); pv[2] = f2tf(vq.z); pv[3] = f2tf(vq.w);
        }
        __syncthreads();

        // S = Q @ K^T   (16 q x 64 keys per warp)
        float s[8][4];
        #pragma unroll
        for (int nt = 0; nt < 8; nt++)
            #pragma unroll
            for (int k = 0; k < 4; k++) s[nt][k] = 0.f;
        #pragma unroll
        for (int ks = 0; ks < 8; ks++)
            #pragma unroll
            for (int nt = 0; nt < 8; nt++) {
                unsigned b0 = K_s[(nt * 8 + tq) * KVP + ks * 8 + tr];
                unsigned b1 = K_s[(nt * 8 + tq) * KVP + ks * 8 + tr + 4];
                mma_tf32(s[nt], qa[ks][0], qa[ks][1], qa[ks][2], qa[ks][3], b0, b1);
            }

        // online softmax (rows tq and tq+8)
        float mx0 = -1e30f, mx1 = -1e30f;
        #pragma unroll
        for (int nt = 0; nt < 8; nt++) {
            mx0 = fmaxf(mx0, fmaxf(s[nt][0], s[nt][1]));
            mx1 = fmaxf(mx1, fmaxf(s[nt][2], s[nt][3]));
        }
        mx0 = fmaxf(mx0, __shfl_xor_sync(0xffffffffu, mx0, 1));
        mx0 = fmaxf(mx0, __shfl_xor_sync(0xffffffffu, mx0, 2));
        mx1 = fmaxf(mx1, __shfl_xor_sync(0xffffffffu, mx1, 1));
        mx1 = fmaxf(mx1, __shfl_xor_sync(0xffffffffu, mx1, 2));
        float nm0 = fmaxf(m0, mx0), nm1 = fmaxf(m1, mx1);
        float al0 = __expf(m0 - nm0), al1 = __expf(m1 - nm1);
        m0 = nm0; m1 = nm1;
        float rs0 = 0.f, rs1 = 0.f;
        #pragma unroll
        for (int nt = 0; nt < 8; nt++) {
            s[nt][0] = __expf(s[nt][0] - m0);
            s[nt][1] = __expf(s[nt][1] - m0);
            s[nt][2] = __expf(s[nt][2] - m1);
            s[nt][3] = __expf(s[nt][3] - m1);
            rs0 += s[nt][0] + s[nt][1];
            rs1 += s[nt][2] + s[nt][3];
        }
        rs0 += __shfl_xor_sync(0xffffffffu, rs0, 1);
        rs0 += __shfl_xor_sync(0xffffffffu, rs0, 2);
        rs1 += __shfl_xor_sync(0xffffffffu, rs1, 1);
        rs1 += __shfl_xor_sync(0xffffffffu, rs1, 2);
        l0 = l0 * al0 + rs0;
        l1 = l1 * al1 + rs1;
        #pragma unroll
        for (int nt = 0; nt < 8; nt++) {
            o[nt][0] *= al0; o[nt][1] *= al0;
            o[nt][2] *= al1; o[nt][3] *= al1;
        }

        // P -> smem (reshape C-frag -> A-frag), per-warp private region
        #pragma unroll
        for (int nt = 0; nt < 8; nt++) {
            Pw[tq * PP + nt * 8 + 2 * tr]           = f2tf(s[nt][0]);
            Pw[tq * PP + nt * 8 + 2 * tr + 1]       = f2tf(s[nt][1]);
            Pw[(tq + 8) * PP + nt * 8 + 2 * tr]     = f2tf(s[nt][2]);
            Pw[(tq + 8) * PP + nt * 8 + 2 * tr + 1] = f2tf(s[nt][3]);
        }
        __syncwarp();

        // O += P @ V
        #pragma unroll
        for (int ks = 0; ks < 8; ks++) {
            unsigned a0 = Pw[tq * PP + ks * 8 + tr];
            unsigned a1 = Pw[(tq + 8) * PP + ks * 8 + tr];
            unsigned a2 = Pw[tq * PP + ks * 8 + tr + 4];
            unsigned a3 = Pw[(tq + 8) * PP + ks * 8 + tr + 4];
            #pragma unroll
            for (int nt = 0; nt < 8; nt++) {
                unsigned b0 = V_s[(ks * 8 + tr) * KVP + nt * 8 + tq];
                unsigned b1 = V_s[(ks * 8 + tr + 4) * KVP + nt * 8 + tq];
                mma_tf32(o[nt], a0, a1, a2, a3, b0, b1);
            }
        }
    }

    // normalize + store
    float inv0 = 1.f / l0, inv1 = 1.f / l1;
    float* ob = g_ao + (size_t)(b * T_ + qrow) * C_ + h * HD;
    #pragma unroll
    for (int nt = 0; nt < 8; nt++) {
        *(float2*)&ob[(size_t)tq * C_ + nt * 8 + 2 * tr] =
            make_float2(o[nt][0] * inv0, o[nt][1] * inv0);
        *(float2*)&ob[(size_t)(tq + 8) * C_ + nt * 8 + 2 * tr] =
            make_float2(o[nt][2] * inv1, o[nt][3] * inv1);
    }
}

// ---------------- launch ----------------
extern "C" void kernel_launch(void* const* d_in, const int* in_sizes, int n_in,
                              void* d_out, int out_size) {
    const float* x    = (const float*)d_in[0];
    const float* kc   = (const float*)d_in[1];
    const float* vc   = (const float*)d_in[2];
    const int*   pidx = (const int*)  d_in[3];
    const float* Wq   = (const float*)d_in[4];
    const float* Wk   = (const float*)d_in[5];
    const float* Wv   = (const float*)d_in[6];
    const float* Wo   = (const float*)d_in[7];

    float* out  = (float*)d_out;
    float* kout = out + 2 * 1024 * 1024;
    float* vout = kout + 2 * 4 * 2048 * 64;

    float *gq, *gkn, *gvn, *gao;
    cudaGetSymbolAddress((void**)&gq,  g_q);
    cudaGetSymbolAddress((void**)&gkn, g_kn);
    cudaGetSymbolAddress((void**)&gvn, g_vn);
    cudaGetSymbolAddress((void**)&gao, g_ao);

    size_t smem_g = (size_t)(2 * 128 * AS + 2 * 32 * BS) * 4;   // 71680
    size_t smem_a = (size_t)(2 * 64 * KVP + 8 * 16 * PP) * 4;   // 71680
    cudaFuncSetAttribute(gemm_tf32, cudaFuncAttributeMaxDynamicSharedMemorySize, (int)smem_g);
    cudaFuncSetAttribute(attn_k,    cudaFuncAttributeMaxDynamicSharedMemorySize, (int)smem_a);

    invf_init<<<1, 32>>>();

    dim3 gQ(C_ / 128, ROWS / 128);
    dim3 gKV(KVW / 128, ROWS / 128);
    gemm_tf32<<<gQ, 256, smem_g>>>(x, Wq, gq,  ROWS, C_,  C_);
    gemm_tf32<<<gKV, 256, smem_g>>>(x, Wk, gkn, ROWS, KVW, C_);
    gemm_tf32<<<gKV, 256, smem_g>>>(x, Wv, gvn, ROWS, KVW, C_);

    rope_k<<<(ROWS * 32) / 256, 256>>>(pidx);

    int nkv = B_ * NKV * S_ * HD;
    assemble_kv_k<<<(nkv + 255) / 256, 256>>>(kc, vc, kout, vout);

    dim3 ga(T_ / 128, NH, B_);
    attn_k<<<ga, 256, smem_a>>>(kout, vout);

    gemm_tf32<<<gQ, 256, smem_g>>>(gao, Wo, out, ROWS, C_, C_);
}

// round 3
// speedup vs baseline: 4.4203x; 1.4639x over previous
#include <cuda_runtime.h>
#include <math.h>

#define B_   2
#define T_   1024
#define C_   1024
#define NH   16
#define NKV  4
#define HD   64
#define S_   2048
#define ROWS 2048
#define KVW  (NKV*HD)

// ---------------- scratch ----------------
__device__ float g_q [ROWS * C_];
__device__ float g_ao[ROWS * C_];
__device__ float g_invf[32];
__device__ float g_cos[ROWS * 32];
__device__ float g_sin[ROWS * 32];

// ---------------- helpers ----------------
__device__ __forceinline__ unsigned f2tf(float x) {
    unsigned u;
    asm("cvt.rna.tf32.f32 %0, %1;" : "=r"(u) : "f"(x));
    return u;
}
__device__ __forceinline__ void mma_tf32(float* c,
                                         unsigned a0, unsigned a1, unsigned a2, unsigned a3,
                                         unsigned b0, unsigned b1) {
    asm volatile(
        "mma.sync.aligned.m16n8k8.row.col.f32.tf32.tf32.f32 "
        "{%0,%1,%2,%3}, {%4,%5,%6,%7}, {%8,%9}, {%0,%1,%2,%3};"
        : "+f"(c[0]), "+f"(c[1]), "+f"(c[2]), "+f"(c[3])
        : "r"(a0), "r"(a1), "r"(a2), "r"(a3), "r"(b0), "r"(b1));
}
__device__ __forceinline__ void cpa16(unsigned s, const float* g) {
    asm volatile("cp.async.ca.shared.global [%0], [%1], 16;" :: "r"(s), "l"(g));
}
__device__ __forceinline__ void cpa_commit() { asm volatile("cp.async.commit_group;"); }

// ---------------- GEMM core: 128M x 64N tile, 128 threads, K=1024, cp.async x2 ----------------
#define AS 36
#define BS 72
#define GSM ((2*128*AS + 2*32*BS) * 4)   // 55296 B

__device__ __forceinline__ void gemm_main(const float* __restrict__ A,
                                          const float* __restrict__ Bw,
                                          int ldB, int m0, int n0,
                                          float acc[2][8][4], float* smf) {
    float* A_s = smf;                 // [2][128][AS]
    float* B_s = smf + 2 * 128 * AS;  // [2][32][BS]
    const int tid = threadIdx.x;
    unsigned aBase = (unsigned)__cvta_generic_to_shared(A_s);
    unsigned bBase = (unsigned)__cvta_generic_to_shared(B_s);

    const int arow = tid >> 3, ac4 = (tid & 7) << 2;
    const int brow = tid >> 4, bc4 = (tid & 15) << 2;

    // prologue: chunk 0 -> buf 0
    #pragma unroll
    for (int i = 0; i < 8; i++)
        cpa16(aBase + (((arow + i * 16) * AS + ac4) << 2),
              &A[(size_t)(m0 + arow + i * 16) * 1024 + ac4]);
    #pragma unroll
    for (int i = 0; i < 4; i++)
        cpa16(bBase + (((brow + i * 8) * BS + bc4) << 2),
              &Bw[(size_t)(brow + i * 8) * ldB + n0 + bc4]);
    cpa_commit();

    const int lane = tid & 31, warp = tid >> 5;
    const int tq = lane >> 2, tr = lane & 3;
    int buf = 0;
    for (int c = 0; c < 32; c++) {
        if (c < 31) {
            int kc = (c + 1) * 32;
            int nb = buf ^ 1;
            #pragma unroll
            for (int i = 0; i < 8; i++)
                cpa16(aBase + ((((nb * 128) + arow + i * 16) * AS + ac4) << 2),
                      &A[(size_t)(m0 + arow + i * 16) * 1024 + kc + ac4]);
            #pragma unroll
            for (int i = 0; i < 4; i++)
                cpa16(bBase + ((((nb * 32) + brow + i * 8) * BS + bc4) << 2),
                      &Bw[(size_t)(kc + brow + i * 8) * ldB + n0 + bc4]);
            cpa_commit();
            asm volatile("cp.async.wait_group 1;");
        } else {
            asm volatile("cp.async.wait_group 0;");
        }
        __syncthreads();

        const float* Ab = A_s + buf * 128 * AS;
        const float* Bb = B_s + buf * 32 * BS;
        #pragma unroll
        for (int ks = 0; ks < 4; ks++) {
            unsigned a[2][4];
            #pragma unroll
            for (int mt = 0; mt < 2; mt++) {
                const float* p = &Ab[(warp * 32 + mt * 16 + tq) * AS + ks * 8 + tr];
                a[mt][0] = f2tf(p[0]);
                a[mt][1] = f2tf(p[8 * AS]);
                a[mt][2] = f2tf(p[4]);
                a[mt][3] = f2tf(p[8 * AS + 4]);
            }
            #pragma unroll
            for (int nt = 0; nt < 8; nt++) {
                unsigned b0 = f2tf(Bb[(ks * 8 + tr) * BS + nt * 8 + tq]);
                unsigned b1 = f2tf(Bb[(ks * 8 + tr + 4) * BS + nt * 8 + tq]);
                mma_tf32(acc[0][nt], a[0][0], a[0][1], a[0][2], a[0][3], b0, b1);
                mma_tf32(acc[1][nt], a[1][0], a[1][1], a[1][2], a[1][3], b0, b1);
            }
        }
        __syncthreads();
        buf ^= 1;
    }
}

// rope rotate in registers: pairs (nt, nt+4)
__device__ __forceinline__ void rope_acc(float acc[2][8][4], int m0) {
    const int lane = threadIdx.x & 31, warp = threadIdx.x >> 5;
    const int tq = lane >> 2, tr = lane & 3;
    #pragma unroll
    for (int mt = 0; mt < 2; mt++) {
        int r0 = m0 + warp * 32 + mt * 16 + tq;
        int r1 = r0 + 8;
        #pragma unroll
        for (int nt = 0; nt < 4; nt++) {
            int i0 = nt * 8 + 2 * tr;
            float2 c0 = *(const float2*)&g_cos[r0 * 32 + i0];
            float2 s0 = *(const float2*)&g_sin[r0 * 32 + i0];
            float2 c1 = *(const float2*)&g_cos[r1 * 32 + i0];
            float2 s1 = *(const float2*)&g_sin[r1 * 32 + i0];
            float x1, x2;
            x1 = acc[mt][nt][0]; x2 = acc[mt][nt + 4][0];
            acc[mt][nt][0] = x1 * c0.x - x2 * s0.x;  acc[mt][nt + 4][0] = x2 * c0.x + x1 * s0.x;
            x1 = acc[mt][nt][1]; x2 = acc[mt][nt + 4][1];
            acc[mt][nt][1] = x1 * c0.y - x2 * s0.y;  acc[mt][nt + 4][1] = x2 * c0.y + x1 * s0.y;
            x1 = acc[mt][nt][2]; x2 = acc[mt][nt + 4][2];
            acc[mt][nt][2] = x1 * c1.x - x2 * s1.x;  acc[mt][nt + 4][2] = x2 * c1.x + x1 * s1.x;
            x1 = acc[mt][nt][3]; x2 = acc[mt][nt + 4][3];
            acc[mt][nt][3] = x1 * c1.y - x2 * s1.y;  acc[mt][nt + 4][3] = x2 * c1.y + x1 * s1.y;
        }
    }
}

// ---------------- merged QKV projection (+rope, +scatter) ----------------
__global__ __launch_bounds__(128, 4) void qkv_gemm(const float* __restrict__ x,
                                                   const float* __restrict__ Wq,
                                                   const float* __restrict__ Wk,
                                                   const float* __restrict__ Wv,
                                                   float* __restrict__ kout,
                                                   float* __restrict__ vout) {
    extern __shared__ float smf[];
    const int bx = blockIdx.x, m0 = blockIdx.y * 128;
    const float* Bw; int ldB, n0, mode;
    if (bx < 16)      { Bw = Wq; ldB = 1024; n0 = bx * 64;        mode = 0; }
    else if (bx < 20) { Bw = Wk; ldB = 256;  n0 = (bx - 16) * 64; mode = 1; }
    else              { Bw = Wv; ldB = 256;  n0 = (bx - 20) * 64; mode = 2; }

    float acc[2][8][4];
    #pragma unroll
    for (int i = 0; i < 2; i++)
        #pragma unroll
        for (int j = 0; j < 8; j++)
            #pragma unroll
            for (int k = 0; k < 4; k++) acc[i][j][k] = 0.f;

    gemm_main(x, Bw, ldB, m0, n0, acc, smf);

    if (mode != 2) rope_acc(acc, m0);

    const int lane = threadIdx.x & 31, warp = threadIdx.x >> 5;
    const int tq = lane >> 2, tr = lane & 3;
    #pragma unroll
    for (int mt = 0; mt < 2; mt++) {
        int r = m0 + warp * 32 + mt * 16 + tq;
        if (mode == 0) {
            float* p0 = &g_q[(size_t)r * C_ + n0];
            float* p1 = &g_q[(size_t)(r + 8) * C_ + n0];
            #pragma unroll
            for (int nt = 0; nt < 8; nt++) {
                *(float2*)&p0[nt * 8 + 2 * tr] = make_float2(acc[mt][nt][0], acc[mt][nt][1]);
                *(float2*)&p1[nt * 8 + 2 * tr] = make_float2(acc[mt][nt][2], acc[mt][nt][3]);
            }
        } else {
            int b = r >> 10, t = r & 1023;
            int kv = (mode == 1) ? (bx - 16) : (bx - 20);
            float* dst = (mode == 1) ? kout : vout;
            float* p0 = &dst[(size_t)((b * NKV + kv) * S_ + 1024 + t) * HD];
            float* p1 = &dst[(size_t)((b * NKV + kv) * S_ + 1024 + t + 8) * HD];
            #pragma unroll
            for (int nt = 0; nt < 8; nt++) {
                *(float2*)&p0[nt * 8 + 2 * tr] = make_float2(acc[mt][nt][0], acc[mt][nt][1]);
                *(float2*)&p1[nt * 8 + 2 * tr] = make_float2(acc[mt][nt][2], acc[mt][nt][3]);
            }
        }
    }
}

// ---------------- O projection ----------------
__global__ __launch_bounds__(128, 4) void o_gemm(const float* __restrict__ A,
                                                 const float* __restrict__ Wo,
                                                 float* __restrict__ out) {
    extern __shared__ float smf[];
    const int m0 = blockIdx.y * 128, n0 = blockIdx.x * 64;
    float acc[2][8][4];
    #pragma unroll
    for (int i = 0; i < 2; i++)
        #pragma unroll
        for (int j = 0; j < 8; j++)
            #pragma unroll
            for (int k = 0; k < 4; k++) acc[i][j][k] = 0.f;

    gemm_main(A, Wo, 1024, m0, n0, acc, smf);

    const int lane = threadIdx.x & 31, warp = threadIdx.x >> 5;
    const int tq = lane >> 2, tr = lane & 3;
    #pragma unroll
    for (int mt = 0; mt < 2; mt++) {
        int r = m0 + warp * 32 + mt * 16 + tq;
        float* p0 = &out[(size_t)r * C_ + n0];
        float* p1 = &out[(size_t)(r + 8) * C_ + n0];
        #pragma unroll
        for (int nt = 0; nt < 8; nt++) {
            *(float2*)&p0[nt * 8 + 2 * tr] = make_float2(acc[mt][nt][0], acc[mt][nt][1]);
            *(float2*)&p1[nt * 8 + 2 * tr] = make_float2(acc[mt][nt][2], acc[mt][nt][3]);
        }
    }
}

// ---------------- tables ----------------
__global__ void invf_init() {
    if (threadIdx.x < 32)
        g_invf[threadIdx.x] = (float)pow(10000.0, -(double)threadIdx.x / 32.0);
}
__global__ void rope_tab(const int* __restrict__ pidx) {
    int idx = blockIdx.x * blockDim.x + threadIdx.x;
    if (idx >= ROWS * 32) return;
    int i = idx & 31, row = idx >> 5;
    int p = min(max(pidx[row] + (row & 1023) + 1024, 0), 4095);
    float ang = (float)p * g_invf[i];
    float c, s;
    sincosf(ang, &s, &c);
    g_cos[idx] = c;
    g_sin[idx] = s;
}

// ---------------- cache halves copy ----------------
__global__ void copy_cache(const float* __restrict__ kc, const float* __restrict__ vc,
                           float* __restrict__ kout, float* __restrict__ vout) {
    int idx = blockIdx.x * blockDim.x + threadIdx.x;   // float4 index
    if (idx >= B_ * NKV * 1024 * 16) return;
    int d4 = idx & 15;
    int s  = (idx >> 4) & 1023;
    int bk = idx >> 14;
    int dst = ((bk * S_) + s) * 16 + d4;
    ((float4*)kout)[dst] = ((const float4*)kc)[idx];
    ((float4*)vout)[dst] = ((const float4*)vc)[idx];
}

// ---------------- Flash attention: 128q CTA, shuffle-P, 2 CTAs/SM ----------------
#define KP 68
#define VP 72
#define ASM ((64*KP + 64*VP) * 4)   // 35840 B

__global__ __launch_bounds__(256, 2) void attn_k(const float* __restrict__ kall,
                                                 const float* __restrict__ vall) {
    extern __shared__ unsigned sm[];
    unsigned* K_s = sm;             // [64][KP]
    unsigned* V_s = sm + 64 * KP;   // [64][VP]

    const int tid = threadIdx.x, lane = tid & 31, warp = tid >> 5;
    const int tq = lane >> 2, tr = lane & 3;
    const int qt = blockIdx.x, h = blockIdx.y, b = blockIdx.z;
    const float* kb = kall + (size_t)(b * NKV + (h >> 2)) * S_ * HD;
    const float* vb = vall + (size_t)(b * NKV + (h >> 2)) * S_ * HD;
    const int qrow = qt * 128 + warp * 16;

    unsigned qa[8][4];
    const float* qp = g_q + (size_t)(b * T_ + qrow) * C_ + h * HD;
    #pragma unroll
    for (int ks = 0; ks < 8; ks++) {
        qa[ks][0] = f2tf(qp[(size_t)tq * C_ + ks * 8 + tr] * 0.125f);
        qa[ks][1] = f2tf(qp[(size_t)(tq + 8) * C_ + ks * 8 + tr] * 0.125f);
        qa[ks][2] = f2tf(qp[(size_t)tq * C_ + ks * 8 + tr + 4] * 0.125f);
        qa[ks][3] = f2tf(qp[(size_t)(tq + 8) * C_ + ks * 8 + tr + 4] * 0.125f);
    }

    float m0 = -1e30f, m1 = -1e30f, l0 = 0.f, l1 = 0.f;
    float o[8][4];
    #pragma unroll
    for (int nt = 0; nt < 8; nt++)
        #pragma unroll
        for (int k = 0; k < 4; k++) o[nt][k] = 0.f;

    const int srcA = (lane & 28) | ((lane >> 1) & 1);
    const int srcB = srcA + 2;
    const bool eo = lane & 1;

    for (int c0 = 0; c0 < S_; c0 += 64) {
        __syncthreads();
        #pragma unroll
        for (int i = 0; i < 4; i++) {
            int idx = tid + i * 256;
            int row = idx >> 4, d4 = (idx & 15) << 2;
            float4 kq = *(const float4*)&kb[(size_t)(c0 + row) * HD + d4];
            float4 vq = *(const float4*)&vb[(size_t)(c0 + row) * HD + d4];
            uint4 ku = make_uint4(f2tf(kq.x), f2tf(kq.y), f2tf(kq.z), f2tf(kq.w));
            uint4 vu = make_uint4(f2tf(vq.x), f2tf(vq.y), f2tf(vq.z), f2tf(vq.w));
            *(uint4*)&K_s[row * KP + d4] = ku;
            *(uint4*)&V_s[row * VP + d4] = vu;
        }
        __syncthreads();

        // S = Q @ K^T
        float s[8][4];
        #pragma unroll
        for (int nt = 0; nt < 8; nt++)
            #pragma unroll
            for (int k = 0; k < 4; k++) s[nt][k] = 0.f;
        #pragma unroll
        for (int ks = 0; ks < 8; ks++)
            #pragma unroll
            for (int nt = 0; nt < 8; nt++) {
                unsigned b0 = K_s[(nt * 8 + tq) * KP + ks * 8 + tr];
                unsigned b1 = K_s[(nt * 8 + tq) * KP + ks * 8 + tr + 4];
                mma_tf32(s[nt], qa[ks][0], qa[ks][1], qa[ks][2], qa[ks][3], b0, b1);
            }

        // online softmax
        float mx0 = -1e30f, mx1 = -1e30f;
        #pragma unroll
        for (int nt = 0; nt < 8; nt++) {
            mx0 = fmaxf(mx0, fmaxf(s[nt][0], s[nt][1]));
            mx1 = fmaxf(mx1, fmaxf(s[nt][2], s[nt][3]));
        }
        mx0 = fmaxf(mx0, __shfl_xor_sync(0xffffffffu, mx0, 1));
        mx0 = fmaxf(mx0, __shfl_xor_sync(0xffffffffu, mx0, 2));
        mx1 = fmaxf(mx1, __shfl_xor_sync(0xffffffffu, mx1, 1));
        mx1 = fmaxf(mx1, __shfl_xor_sync(0xffffffffu, mx1, 2));
        float nm0 = fmaxf(m0, mx0), nm1 = fmaxf(m1, mx1);
        float al0 = __expf(m0 - nm0), al1 = __expf(m1 - nm1);
        m0 = nm0; m1 = nm1;
        float rs0 = 0.f, rs1 = 0.f;
        #pragma unroll
        for (int nt = 0; nt < 8; nt++) {
            s[nt][0] = __expf(s[nt][0] - m0);
            s[nt][1] = __expf(s[nt][1] - m0);
            s[nt][2] = __expf(s[nt][2] - m1);
            s[nt][3] = __expf(s[nt][3] - m1);
            rs0 += s[nt][0] + s[nt][1];
            rs1 += s[nt][2] + s[nt][3];
        }
        rs0 += __shfl_xor_sync(0xffffffffu, rs0, 1);
        rs0 += __shfl_xor_sync(0xffffffffu, rs0, 2);
        rs1 += __shfl_xor_sync(0xffffffffu, rs1, 1);
        rs1 += __shfl_xor_sync(0xffffffffu, rs1, 2);
        l0 = l0 * al0 + rs0;
        l1 = l1 * al1 + rs1;
        #pragma unroll
        for (int nt = 0; nt < 8; nt++) {
            o[nt][0] *= al0; o[nt][1] *= al0;
            o[nt][2] *= al1; o[nt][3] *= al1;
        }

        // O += P @ V, with P reshaped C-frag -> A-frag via shuffles
        #pragma unroll
        for (int ks = 0; ks < 8; ks++) {
            unsigned u0 = f2tf(s[ks][0]), u1 = f2tf(s[ks][1]);
            unsigned u2 = f2tf(s[ks][2]), u3 = f2tf(s[ks][3]);
            unsigned xa0 = __shfl_sync(0xffffffffu, u0, srcA);
            unsigned xa1 = __shfl_sync(0xffffffffu, u1, srcA);
            unsigned ya0 = __shfl_sync(0xffffffffu, u2, srcA);
            unsigned ya1 = __shfl_sync(0xffffffffu, u3, srcA);
            unsigned xb0 = __shfl_sync(0xffffffffu, u0, srcB);
            unsigned xb1 = __shfl_sync(0xffffffffu, u1, srcB);
            unsigned yb0 = __shfl_sync(0xffffffffu, u2, srcB);
            unsigned yb1 = __shfl_sync(0xffffffffu, u3, srcB);
            unsigned a0 = eo ? xa1 : xa0;
            unsigned a1 = eo ? ya1 : ya0;
            unsigned a2 = eo ? xb1 : xb0;
            unsigned a3 = eo ? yb1 : yb0;
            #pragma unroll
            for (int dt = 0; dt < 8; dt++) {
                unsigned b0 = V_s[(ks * 8 + tr) * VP + dt * 8 + tq];
                unsigned b1 = V_s[(ks * 8 + tr + 4) * VP + dt * 8 + tq];
                mma_tf32(o[dt], a0, a1, a2, a3, b0, b1);
            }
        }
    }

    float inv0 = 1.f / l0, inv1 = 1.f / l1;
    float* ob = g_ao + (size_t)(b * T_ + qrow) * C_ + h * HD;
    #pragma unroll
    for (int nt = 0; nt < 8; nt++) {
        *(float2*)&ob[(size_t)tq * C_ + nt * 8 + 2 * tr] =
            make_float2(o[nt][0] * inv0, o[nt][1] * inv0);
        *(float2*)&ob[(size_t)(tq + 8) * C_ + nt * 8 + 2 * tr] =
            make_float2(o[nt][2] * inv1, o[nt][3] * inv1);
    }
}

// ---------------- launch ----------------
extern "C" void kernel_launch(void* const* d_in, const int* in_sizes, int n_in,
                              void* d_out, int out_size) {
    const float* x    = (const float*)d_in[0];
    const float* kc   = (const float*)d_in[1];
    const float* vc   = (const float*)d_in[2];
    const int*   pidx = (const int*)  d_in[3];
    const float* Wq   = (const float*)d_in[4];
    const float* Wk   = (const float*)d_in[5];
    const float* Wv   = (const float*)d_in[6];
    const float* Wo   = (const float*)d_in[7];

    float* out  = (float*)d_out;
    float* kout = out + 2 * 1024 * 1024;
    float* vout = kout + 2 * 4 * 2048 * 64;

    float *gq, *gao;
    cudaGetSymbolAddress((void**)&gq,  g_q);
    cudaGetSymbolAddress((void**)&gao, g_ao);

    cudaFuncSetAttribute(qkv_gemm, cudaFuncAttributeMaxDynamicSharedMemorySize, GSM);
    cudaFuncSetAttribute(o_gemm,   cudaFuncAttributeMaxDynamicSharedMemorySize, GSM);
    cudaFuncSetAttribute(attn_k,   cudaFuncAttributeMaxDynamicSharedMemorySize, ASM);

    invf_init<<<1, 32>>>();
    rope_tab<<<(ROWS * 32) / 256, 256>>>(pidx);

    dim3 gqkv(24, 16);
    qkv_gemm<<<gqkv, 128, GSM>>>(x, Wq, Wk, Wv, kout, vout);

    int nc = B_ * NKV * 1024 * 16;
    copy_cache<<<(nc + 255) / 256, 256>>>(kc, vc, kout, vout);

    dim3 ga(T_ / 128, NH, B_);
    attn_k<<<ga, 256, ASM>>>(kout, vout);

    dim3 go(16, 16);
    o_gemm<<<go, 128, GSM>>>(gao, Wo, out);
}